// round 3
// baseline (speedup 1.0000x reference)
#include <cuda_runtime.h>
#include <cuda_bf16.h>
#include <math.h>

#define NA 4096
#define NP 8192
#define NT 4096
#define NC 2048

// ---------------- device scratch ----------------
__device__ float g_ha[NA*128];
__device__ float g_hp[NP*128];
__device__ float g_ht[NT*128];
__device__ float g_hc[NC*128];
__device__ float g_xt[NA*128];
__device__ float g_an[NA*128];
__device__ float g_snp[NP*128];
__device__ float g_snt[NT*128];
__device__ float g_snc[NC*128];
__device__ float g_gp[NP*128];
__device__ float g_gt[NT*128];
__device__ float g_gc[NC*128];
__device__ float g_alsp[NP];
__device__ float g_alst[NT];
__device__ float g_alsc[NC];
__device__ float g_ald[3*NA];
__device__ float g_wdv[3*128];
__device__ float g_mxs[3];
__device__ float g_acc[3*NA*128];
__device__ float g_den[3*NA];
__device__ float g_ssum[4];
__device__ float g_alpha[4];
__device__ float g_agg1[NA*128];
__device__ float g_deg[NA];
__device__ float g_h1[NA*256];
__device__ float g_agg2[NA*256];

// ---------------- utility kernels ----------------
__global__ void zero_kernel(float* __restrict__ p, int n) {
    int i = blockIdx.x * blockDim.x + threadIdx.x;
    if (i < n) p[i] = 0.f;
}

// Y[r,:] = X[r,:] / max(||X[r,:]||, 1e-12); D=128, one block (128 thr) per row
__global__ void rownorm_kernel(const float* __restrict__ X, float* __restrict__ Y) {
    int r = blockIdx.x;
    int t = threadIdx.x;
    float v = X[(size_t)r * 128 + t];
    float s = v * v;
    #pragma unroll
    for (int o = 16; o; o >>= 1) s += __shfl_xor_sync(0xffffffffu, s, o);
    __shared__ float ws[4];
    if ((t & 31) == 0) ws[t >> 5] = s;
    __syncthreads();
    float tot = ws[0] + ws[1] + ws[2] + ws[3];
    float scale = 1.0f / fmaxf(sqrtf(tot), 1e-12f);
    Y[(size_t)r * 128 + t] = v * scale;
}

// y[r] = dot(X[r,:], v); D=128, one block per row
__global__ void matvec_kernel(const float* __restrict__ X, const float* __restrict__ v,
                              float* __restrict__ y) {
    int r = blockIdx.x;
    int t = threadIdx.x;
    float s = X[(size_t)r * 128 + t] * v[t];
    #pragma unroll
    for (int o = 16; o; o >>= 1) s += __shfl_xor_sync(0xffffffffu, s, o);
    __shared__ float ws[4];
    if ((t & 31) == 0) ws[t >> 5] = s;
    __syncthreads();
    if (t == 0) y[r] = ws[0] + ws[1] + ws[2] + ws[3];
}

// out3[i][k] = sum_c W3[i][k][c] * a3[i][c]; grid=3, block=128
__global__ void wvec_kernel(const float* __restrict__ W3, const float* __restrict__ a3,
                            float* __restrict__ out3) {
    int i = blockIdx.x;
    int k = threadIdx.x;
    __shared__ float sa[128];
    sa[k] = a3[i * 128 + k];
    __syncthreads();
    const float* W = W3 + (size_t)i * 128 * 128 + (size_t)k * 128;
    float s = 0.f;
    #pragma unroll 8
    for (int c = 0; c < 128; c++) s += W[c] * sa[c];
    out3[i * 128 + k] = s;
}

__global__ void maxred_kernel(const float* __restrict__ a, int n, float* __restrict__ out) {
    int t = threadIdx.x;
    float m = -3.0e38f;
    for (int i = t; i < n; i += 256) m = fmaxf(m, a[i]);
    #pragma unroll
    for (int o = 16; o; o >>= 1) m = fmaxf(m, __shfl_xor_sync(0xffffffffu, m, o));
    __shared__ float ws[8];
    if ((t & 31) == 0) ws[t >> 5] = m;
    __syncthreads();
    if (t == 0) {
        float mm = ws[0];
        #pragma unroll
        for (int i = 1; i < 8; i++) mm = fmaxf(mm, ws[i]);
        out[0] = mm;
    }
}

// ---------------- generic tiled GEMM: C = A@W (+bias) (+C) (relu) ----------------
// tile 64 x 128 per block, 256 threads, BK=16. thread: 8 rows x 4 cols.
__global__ __launch_bounds__(256) void linear_kernel(
    const float* __restrict__ A, const float* __restrict__ W,
    const float* __restrict__ bias, float* __restrict__ C,
    int M, int K, int N, int addC, int doRelu)
{
    __shared__ float As[16][64];
    __shared__ float Ws[16][128];
    int rb = blockIdx.x * 64;
    int cb = blockIdx.y * 128;
    int t = threadIdx.x;
    int cg = t & 31;      // cols cg*4
    int rg = t >> 5;      // rows rg*8
    float acc[8][4];
    #pragma unroll
    for (int i = 0; i < 8; i++)
        #pragma unroll
        for (int j = 0; j < 4; j++) acc[i][j] = 0.f;

    for (int k0 = 0; k0 < K; k0 += 16) {
        for (int i = t; i < 1024; i += 256) {
            int r = i >> 4, kk = i & 15;
            int kg = k0 + kk;
            As[kk][r] = (kg < K) ? A[(size_t)(rb + r) * K + kg] : 0.f;
        }
        for (int i = t; i < 2048; i += 256) {
            int kk = i >> 7, c = i & 127;
            int kg = k0 + kk;
            Ws[kk][c] = (kg < K && (cb + c) < N) ? W[(size_t)kg * N + cb + c] : 0.f;
        }
        __syncthreads();
        #pragma unroll
        for (int kk = 0; kk < 16; kk++) {
            float4 w4 = *(float4*)&Ws[kk][cg * 4];
            float a[8];
            #pragma unroll
            for (int i = 0; i < 8; i++) a[i] = As[kk][rg * 8 + i];
            #pragma unroll
            for (int i = 0; i < 8; i++) {
                acc[i][0] += a[i] * w4.x;
                acc[i][1] += a[i] * w4.y;
                acc[i][2] += a[i] * w4.z;
                acc[i][3] += a[i] * w4.w;
            }
        }
        __syncthreads();
    }
    #pragma unroll
    for (int i = 0; i < 8; i++) {
        int row = rb + rg * 8 + i;
        if (row >= M) continue;
        #pragma unroll
        for (int j = 0; j < 4; j++) {
            int col = cb + cg * 4 + j;
            if (col < N) {
                float v = acc[i][j];
                if (bias) v += bias[col];
                if (addC) v += C[(size_t)row * N + col];
                if (doRelu) v = fmaxf(v, 0.f);
                C[(size_t)row * N + col] = v;
            }
        }
    }
}

// ---------------- fused hetero GAT kernel ----------------
// grid 448 = 7 (type,segment) combos x 64 author blocks. 256 threads.
// Per block: 64 author rows, loop 64 chunks of 32 src rows (segment = 2048).
__global__ __launch_bounds__(256, 2) void hetero_kernel(
    const float* __restrict__ an, const float* __restrict__ ald3,
    const float* __restrict__ mxs,
    const float* __restrict__ snp, const float* __restrict__ gp, const float* __restrict__ alsp,
    const float* __restrict__ snt, const float* __restrict__ gt, const float* __restrict__ alst,
    const float* __restrict__ snc, const float* __restrict__ gc, const float* __restrict__ alsc,
    float* __restrict__ acc, float* __restrict__ deng)
{
    extern __shared__ float sm[];
    float* sAN  = sm;              // [64][128]  8192
    float* sSNT = sm + 8192;       // [128][36]  4608 (transposed, padded)
    float* sHS  = sm + 12800;      // [32][128]  4096
    float* sW   = sm + 16896;      // [64][33]   2112
    float* sALD = sm + 19008;      // 64
    float* sALS = sm + 19072;      // 32
    float* sDEN = sm + 19104;      // 64

    int bx = blockIdx.x;
    int combo = bx >> 6;
    int ab = bx & 63;
    int type, seg0;
    const float *sn, *hs, *als;
    if (combo < 4)      { type = 0; seg0 = combo << 11;       sn = snp; hs = gp; als = alsp; }
    else if (combo < 6) { type = 1; seg0 = (combo - 4) << 11; sn = snt; hs = gt; als = alst; }
    else                { type = 2; seg0 = 0;                 sn = snc; hs = gc; als = alsc; }

    int t = threadIdx.x;
    int cg = t & 15;         // phase1 cols cg*2, phase2 cols cg*8
    int rg = t >> 4;         // rows rg*4
    int r0g = ab << 6;
    float mx = mxs[type];

    for (int i = t; i < 2048; i += 256) {
        int r = i >> 5, q = i & 31;
        *(float4*)&sAN[r * 128 + q * 4] =
            *(const float4*)&an[(size_t)(r0g + r) * 128 + q * 4];
    }
    if (t < 64) { sALD[t] = ald3[type * NA + r0g + t]; sDEN[t] = 0.f; }

    float num[4][8];
    #pragma unroll
    for (int i = 0; i < 4; i++)
        #pragma unroll
        for (int j = 0; j < 8; j++) num[i][j] = 0.f;

    __syncthreads();

    for (int ch = 0; ch < 64; ch++) {
        int j0 = seg0 + (ch << 5);
        // load SN^T and HS chunk
        for (int i = t; i < 1024; i += 256) {
            int j = i >> 5, q = i & 31;
            float4 v = *(const float4*)&sn[(size_t)(j0 + j) * 128 + q * 4];
            sSNT[(q * 4 + 0) * 36 + j] = v.x;
            sSNT[(q * 4 + 1) * 36 + j] = v.y;
            sSNT[(q * 4 + 2) * 36 + j] = v.z;
            sSNT[(q * 4 + 3) * 36 + j] = v.w;
            *(float4*)&sHS[j * 128 + q * 4] =
                *(const float4*)&hs[(size_t)(j0 + j) * 128 + q * 4];
        }
        if (t < 32) sALS[t] = als[j0 + t];
        __syncthreads();

        // phase 1: S[4][2] = AN[rg*4+i][:] . SN[cg*2+jj][:]
        float S[4][2];
        #pragma unroll
        for (int i = 0; i < 4; i++) { S[i][0] = 0.f; S[i][1] = 0.f; }
        #pragma unroll 2
        for (int k = 0; k < 128; k += 4) {
            float4 A4[4];
            #pragma unroll
            for (int i = 0; i < 4; i++)
                A4[i] = *(float4*)&sAN[(rg * 4 + i) * 128 + k];
            float2 B2[4];
            #pragma unroll
            for (int kk = 0; kk < 4; kk++)
                B2[kk] = *(float2*)&sSNT[(k + kk) * 36 + cg * 2];
            #pragma unroll
            for (int i = 0; i < 4; i++) {
                S[i][0] += A4[i].x * B2[0].x; S[i][0] += A4[i].y * B2[1].x;
                S[i][0] += A4[i].z * B2[2].x; S[i][0] += A4[i].w * B2[3].x;
                S[i][1] += A4[i].x * B2[0].y; S[i][1] += A4[i].y * B2[1].y;
                S[i][1] += A4[i].z * B2[2].y; S[i][1] += A4[i].w * B2[3].y;
            }
        }

        // phase 1.5: weights + row-sum
        float rsum[4];
        #pragma unroll
        for (int i = 0; i < 4; i++) {
            float aldr = sALD[rg * 4 + i];
            float tm = aldr + mx;
            float mrow = tm >= 0.f ? tm : 0.2f * tm;
            rsum[i] = 0.f;
            #pragma unroll
            for (int jj = 0; jj < 2; jj++) {
                float w = 0.f;
                int jgl = j0 + cg * 2 + jj;
                if (S[i][jj] > 0.1f && (r0g + rg * 4 + i) != jgl) {
                    float e0 = aldr + sALS[cg * 2 + jj];
                    float e = e0 >= 0.f ? e0 : 0.2f * e0;
                    w = __expf(e - mrow);
                }
                sW[(rg * 4 + i) * 33 + cg * 2 + jj] = w;
                rsum[i] += w;
            }
        }
        #pragma unroll
        for (int o = 1; o < 16; o <<= 1) {
            #pragma unroll
            for (int i = 0; i < 4; i++)
                rsum[i] += __shfl_xor_sync(0xffffffffu, rsum[i], o);
        }
        if (cg == 0) {
            #pragma unroll
            for (int i = 0; i < 4; i++) sDEN[rg * 4 + i] += rsum[i];
        }
        __syncthreads();

        // phase 2: num[64][128] += W[64][32] @ HS[32][128]
        #pragma unroll 2
        for (int j = 0; j < 32; j++) {
            float wv[4];
            #pragma unroll
            for (int i = 0; i < 4; i++) wv[i] = sW[(rg * 4 + i) * 33 + j];
            float4 h0 = *(float4*)&sHS[j * 128 + cg * 8];
            float4 h1 = *(float4*)&sHS[j * 128 + cg * 8 + 4];
            #pragma unroll
            for (int i = 0; i < 4; i++) {
                num[i][0] += wv[i] * h0.x; num[i][1] += wv[i] * h0.y;
                num[i][2] += wv[i] * h0.z; num[i][3] += wv[i] * h0.w;
                num[i][4] += wv[i] * h1.x; num[i][5] += wv[i] * h1.y;
                num[i][6] += wv[i] * h1.z; num[i][7] += wv[i] * h1.w;
            }
        }
        __syncthreads();
    }

    // accumulate partials
    float* accT = acc + (size_t)type * NA * 128;
    #pragma unroll
    for (int i = 0; i < 4; i++) {
        size_t base = (size_t)(r0g + rg * 4 + i) * 128 + cg * 8;
        #pragma unroll
        for (int j = 0; j < 8; j++)
            atomicAdd(&accT[base + j], num[i][j]);
    }
    if (cg == 0) {
        #pragma unroll
        for (int i = 0; i < 4; i++)
            atomicAdd(&deng[type * NA + r0g + rg * 4 + i], sDEN[rg * 4 + i]);
    }
}

// heter = acc/den + b  (in place); idx over 3*NA*128
__global__ void finalize_kernel(float* __restrict__ acc, const float* __restrict__ den,
                                const float* __restrict__ gb) {
    int idx = blockIdx.x * blockDim.x + threadIdx.x;
    if (idx >= 3 * NA * 128) return;
    int c = idx & 127;
    int dr = idx >> 7;             // type*NA + r
    int type = idx >> 19;
    float d = den[dr];
    float b = gb[type * 128 + c];
    acc[idx] = (d > 0.f) ? acc[idx] / d + b : b;
}

// per-set attention score partial: grid (NA/4, 4), block 256 = 4 rows x 64 cols
__global__ void attscore_kernel(const float* __restrict__ heter, const float* __restrict__ xt,
                                const float* __restrict__ Watt, const float* __restrict__ atts,
                                float* __restrict__ ssum) {
    int set = blockIdx.y;
    const float* X = (set < 3) ? heter + (size_t)set * NA * 128 : xt;
    int rb = blockIdx.x * 4;
    int t = threadIdx.x;
    int c = t & 63;
    __shared__ float xs[4][128];
    for (int i = t; i < 512; i += 256)
        xs[i >> 7][i & 127] = X[(size_t)(rb + (i >> 7)) * 128 + (i & 127)];
    __syncthreads();
    const float* xr = xs[t >> 6];
    float dot = 0.f;
    #pragma unroll 8
    for (int k = 0; k < 128; k++) dot += xr[k] * Watt[k * 64 + c];
    float val = (1.f / (1.f + __expf(-dot))) * atts[set * 64 + c];
    #pragma unroll
    for (int o = 16; o; o >>= 1) val += __shfl_xor_sync(0xffffffffu, val, o);
    __shared__ float ps[8];
    if ((t & 31) == 0) ps[t >> 5] = val;
    __syncthreads();
    if (t == 0) {
        float s = 0.f;
        #pragma unroll
        for (int i = 0; i < 8; i++) s += ps[i];
        atomicAdd(&ssum[set], s);
    }
}

__global__ void alpha_kernel(const float* __restrict__ ssum, float* __restrict__ alpha) {
    if (threadIdx.x == 0) {
        float s[4], m = -3e38f;
        for (int i = 0; i < 4; i++) { s[i] = ssum[i] / (float)NA; m = fmaxf(m, s[i]); }
        float e[4], tot = 0.f;
        for (int i = 0; i < 4; i++) { e[i] = expf(s[i] - m); tot += e[i]; }
        for (int i = 0; i < 4; i++) alpha[i] = e[i] / tot;
    }
}

__global__ void xatt_kernel(const float* __restrict__ heter, const float* __restrict__ xt,
                            const float* __restrict__ alpha, float* __restrict__ out) {
    int idx = blockIdx.x * blockDim.x + threadIdx.x;
    if (idx >= NA * 128) return;
    float v = alpha[0] * heter[idx] + alpha[1] * heter[NA * 128 + idx] +
              alpha[2] * heter[2 * NA * 128 + idx] + alpha[3] * xt[idx];
    out[idx] = v;
}

// ---------------- SAGE ----------------
__global__ void deg_kernel(const int* __restrict__ dst, float* __restrict__ deg, int E) {
    int e = blockIdx.x * blockDim.x + threadIdx.x;
    if (e < E) atomicAdd(&deg[dst[e]], 1.0f);
}

__global__ void scatter_kernel(const float* __restrict__ X, const int* __restrict__ src,
                               const int* __restrict__ dst, float* __restrict__ AGG,
                               int E, int C) {
    int idx = blockIdx.x * blockDim.x + threadIdx.x;
    int per = C >> 2;
    if (idx >= E * per) return;
    int e = idx / per, q = idx - e * per;
    int s = src[e], d = dst[e];
    float4 v = *(const float4*)&X[(size_t)s * C + q * 4];
    float* o = &AGG[(size_t)d * C + q * 4];
    atomicAdd(o + 0, v.x); atomicAdd(o + 1, v.y);
    atomicAdd(o + 2, v.z); atomicAdd(o + 3, v.w);
}

__global__ void rowdiv_kernel(float* __restrict__ AGG, const float* __restrict__ deg,
                              int n, int C) {
    int idx = blockIdx.x * blockDim.x + threadIdx.x;
    if (idx >= n) return;
    int r = idx / C;
    AGG[idx] = AGG[idx] / fmaxf(deg[r], 1.0f);
}

// ---------------- host ----------------
extern "C" void kernel_launch(void* const* d_in, const int* in_sizes, int n_in,
                              void* d_out, int out_size) {
    const float* x_ma = (const float*)d_in[0];
    const float* x_mp = (const float*)d_in[1];
    const float* x_mt = (const float*)d_in[2];
    const float* x_mc = (const float*)d_in[3];
    const float* x_ia = (const float*)d_in[4];
    const int*   edge = (const int*)d_in[5];
    const float* Wla  = (const float*)d_in[6];  const float* bla  = (const float*)d_in[7];
    const float* Wlp  = (const float*)d_in[8];  const float* blp  = (const float*)d_in[9];
    const float* Wlt  = (const float*)d_in[10]; const float* blt  = (const float*)d_in[11];
    const float* Wlc  = (const float*)d_in[12]; const float* blc  = (const float*)d_in[13];
    const float* Wltg = (const float*)d_in[14]; const float* bltg = (const float*)d_in[15];
    const float* gWs  = (const float*)d_in[16];
    const float* gWd  = (const float*)d_in[17];
    const float* gas  = (const float*)d_in[18];
    const float* gad  = (const float*)d_in[19];
    const float* gb   = (const float*)d_in[20];
    const float* Watt = (const float*)d_in[21];
    const float* atts = (const float*)d_in[22];
    const float* W1l  = (const float*)d_in[23]; const float* b1 = (const float*)d_in[24];
    const float* W1r  = (const float*)d_in[25];
    const float* W2l  = (const float*)d_in[26]; const float* b2 = (const float*)d_in[27];
    const float* W2r  = (const float*)d_in[28];

    int E = in_sizes[5] / 2;
    int Ka = in_sizes[0] / NA;
    int Kp = in_sizes[1] / NP;
    int Kt = in_sizes[2] / NT;
    int Kc = in_sizes[3] / NC;
    int Kg = in_sizes[4] / NA;

    float* out_x   = (float*)d_out;
    float* out_att = (float*)d_out + (size_t)NA * 64;

    float *ha,*hp,*ht,*hc,*xt,*an,*snp,*snt,*snc,*gp,*gt,*gc;
    float *alsp,*alst,*alsc,*ald,*wdv,*mxs,*acc,*den,*ssum,*alpha,*agg1,*deg,*h1,*agg2;
    cudaGetSymbolAddress((void**)&ha,   g_ha);
    cudaGetSymbolAddress((void**)&hp,   g_hp);
    cudaGetSymbolAddress((void**)&ht,   g_ht);
    cudaGetSymbolAddress((void**)&hc,   g_hc);
    cudaGetSymbolAddress((void**)&xt,   g_xt);
    cudaGetSymbolAddress((void**)&an,   g_an);
    cudaGetSymbolAddress((void**)&snp,  g_snp);
    cudaGetSymbolAddress((void**)&snt,  g_snt);
    cudaGetSymbolAddress((void**)&snc,  g_snc);
    cudaGetSymbolAddress((void**)&gp,   g_gp);
    cudaGetSymbolAddress((void**)&gt,   g_gt);
    cudaGetSymbolAddress((void**)&gc,   g_gc);
    cudaGetSymbolAddress((void**)&alsp, g_alsp);
    cudaGetSymbolAddress((void**)&alst, g_alst);
    cudaGetSymbolAddress((void**)&alsc, g_alsc);
    cudaGetSymbolAddress((void**)&ald,  g_ald);
    cudaGetSymbolAddress((void**)&wdv,  g_wdv);
    cudaGetSymbolAddress((void**)&mxs,  g_mxs);
    cudaGetSymbolAddress((void**)&acc,  g_acc);
    cudaGetSymbolAddress((void**)&den,  g_den);
    cudaGetSymbolAddress((void**)&ssum, g_ssum);
    cudaGetSymbolAddress((void**)&alpha,g_alpha);
    cudaGetSymbolAddress((void**)&agg1, g_agg1);
    cudaGetSymbolAddress((void**)&deg,  g_deg);
    cudaGetSymbolAddress((void**)&h1,   g_h1);
    cudaGetSymbolAddress((void**)&agg2, g_agg2);

    dim3 blk(256);

    // dimension transforms
    linear_kernel<<<dim3(NA/64,1),blk>>>(x_ma, Wla,  bla,  ha, NA, Ka, 128, 0, 0);
    linear_kernel<<<dim3(NP/64,1),blk>>>(x_mp, Wlp,  blp,  hp, NP, Kp, 128, 0, 0);
    linear_kernel<<<dim3(NT/64,1),blk>>>(x_mt, Wlt,  blt,  ht, NT, Kt, 128, 0, 0);
    linear_kernel<<<dim3(NC/64,1),blk>>>(x_mc, Wlc,  blc,  hc, NC, Kc, 128, 0, 0);
    linear_kernel<<<dim3(NA/64,1),blk>>>(x_ia, Wltg, bltg, xt, NA, Kg, 128, 0, 0);
    // GAT source transforms h_s = h @ Ws_i
    linear_kernel<<<dim3(NP/64,1),blk>>>(hp, gWs + 0*16384, nullptr, gp, NP, 128, 128, 0, 0);
    linear_kernel<<<dim3(NT/64,1),blk>>>(ht, gWs + 1*16384, nullptr, gt, NT, 128, 128, 0, 0);
    linear_kernel<<<dim3(NC/64,1),blk>>>(hc, gWs + 2*16384, nullptr, gc, NC, 128, 128, 0, 0);
    // row-normalized features for cosine similarity
    rownorm_kernel<<<NA,128>>>(ha, an);
    rownorm_kernel<<<NP,128>>>(hp, snp);
    rownorm_kernel<<<NT,128>>>(ht, snt);
    rownorm_kernel<<<NC,128>>>(hc, snc);
    // attention scalars
    wvec_kernel<<<3,128>>>(gWd, gad, wdv);
    matvec_kernel<<<NA,128>>>(ha, wdv + 0,   ald + 0*NA);
    matvec_kernel<<<NA,128>>>(ha, wdv + 128, ald + 1*NA);
    matvec_kernel<<<NA,128>>>(ha, wdv + 256, ald + 2*NA);
    matvec_kernel<<<NP,128>>>(gp, gas + 0,   alsp);
    matvec_kernel<<<NT,128>>>(gt, gas + 128, alst);
    matvec_kernel<<<NC,128>>>(gc, gas + 256, alsc);
    maxred_kernel<<<1,256>>>(alsp, NP, mxs + 0);
    maxred_kernel<<<1,256>>>(alst, NT, mxs + 1);
    maxred_kernel<<<1,256>>>(alsc, NC, mxs + 2);
    // zero accumulators
    zero_kernel<<<(3*NA*128)/256,256>>>(acc, 3*NA*128);
    zero_kernel<<<(3*NA+255)/256,256>>>(den, 3*NA);
    zero_kernel<<<1,32>>>(ssum, 4);
    zero_kernel<<<(NA*128)/256,256>>>(agg1, NA*128);
    zero_kernel<<<(NA+255)/256,256>>>(deg, NA);
    zero_kernel<<<(NA*256)/256,256>>>(agg2, NA*256);
    // fused hetero GAT
    cudaFuncSetAttribute(hetero_kernel, cudaFuncAttributeMaxDynamicSharedMemorySize, 19168*4);
    hetero_kernel<<<448,256,19168*4>>>(an, ald, mxs, snp, gp, alsp,
                                       snt, gt, alst, snc, gc, alsc, acc, den);
    finalize_kernel<<<(3*NA*128)/256,256>>>(acc, den, gb);
    // attention-info mixing
    attscore_kernel<<<dim3(NA/4,4),256>>>(acc, xt, Watt, atts, ssum);
    alpha_kernel<<<1,32>>>(ssum, alpha);
    xatt_kernel<<<(NA*128)/256,256>>>(acc, xt, alpha, out_att);
    // GraphSAGE
    deg_kernel<<<(E+255)/256,256>>>(edge + E, deg, E);
    scatter_kernel<<<(E*32)/256,256>>>(ha, edge, edge + E, agg1, E, 128);
    rowdiv_kernel<<<(NA*128)/256,256>>>(agg1, deg, NA*128, 128);
    linear_kernel<<<dim3(NA/64,2),blk>>>(agg1, W1l, b1,      h1, NA, 128, 256, 0, 0);
    linear_kernel<<<dim3(NA/64,2),blk>>>(ha,   W1r, nullptr, h1, NA, 128, 256, 1, 1);
    scatter_kernel<<<(E*64)/256,256>>>(h1, edge, edge + E, agg2, E, 256);
    rowdiv_kernel<<<(NA*256)/256,256>>>(agg2, deg, NA*256, 256);
    linear_kernel<<<dim3(NA/64,1),blk>>>(agg2, W2l, b2,      out_x, NA, 256, 64, 0, 0);
    linear_kernel<<<dim3(NA/64,1),blk>>>(h1,   W2r, nullptr, out_x, NA, 256, 64, 1, 0);
}

// round 4
// speedup vs baseline: 1.1975x; 1.1975x over previous
#include <cuda_runtime.h>
#include <math.h>

#define NA 4096
#define NP 8192
#define NT 4096
#define NC 2048
typedef unsigned long long ull;

__device__ float g_ha[NA*128];
__device__ float g_hp[NP*128];
__device__ float g_ht[NT*128];
__device__ float g_hc[NC*128];
__device__ float g_xt[NA*128];
__device__ float g_an[NA*128];
__device__ float g_snp[NP*128];
__device__ float g_snt[NT*128];
__device__ float g_snc[NC*128];
__device__ float g_gp[NP*128];
__device__ float g_gt[NT*128];
__device__ float g_gc[NC*128];
__device__ float g_alsp[NP];
__device__ float g_alst[NT];
__device__ float g_alsc[NC];
__device__ float g_ald[3*NA];
__device__ float g_wdv[3*128];
__device__ float g_mxs[3];
__device__ float g_acc[3*NA*128];
__device__ float g_den[3*NA];
__device__ float g_ssum[4];
__device__ float g_alpha[4];
__device__ float g_agg1[NA*128];
__device__ float g_deg[NA];
__device__ float g_h1[NA*256];
__device__ float g_q[NA*64];
__device__ float g_aggq[NA*64];

__device__ __forceinline__ void fma2(ull& d, ull a, ull b) {
    asm("fma.rn.f32x2 %0, %1, %2, %0;" : "+l"(d) : "l"(a), "l"(b));
}
__device__ __forceinline__ ull pack2(float x, float y) {
    ull r; asm("mov.b64 %0, {%1, %2};" : "=l"(r) : "f"(x), "f"(y)); return r;
}
__device__ __forceinline__ float2 unpack2(ull v) {
    float2 r; asm("mov.b64 {%0, %1}, %2;" : "=f"(r.x), "=f"(r.y) : "l"(v)); return r;
}

__global__ void zero_kernel(float* __restrict__ p, int n) {
    int i = blockIdx.x * blockDim.x + threadIdx.x;
    if (i < n) p[i] = 0.f;
}

__global__ void rownorm_kernel(const float* __restrict__ X, float* __restrict__ Y) {
    int r = blockIdx.x, t = threadIdx.x;
    float v = X[(size_t)r * 128 + t];
    float s = v * v;
    #pragma unroll
    for (int o = 16; o; o >>= 1) s += __shfl_xor_sync(0xffffffffu, s, o);
    __shared__ float ws[4];
    if ((t & 31) == 0) ws[t >> 5] = s;
    __syncthreads();
    float tot = ws[0] + ws[1] + ws[2] + ws[3];
    Y[(size_t)r * 128 + t] = v / fmaxf(sqrtf(tot), 1e-12f);
}

__global__ void matvec_kernel(const float* __restrict__ X, const float* __restrict__ v,
                              float* __restrict__ y) {
    int r = blockIdx.x, t = threadIdx.x;
    float s = X[(size_t)r * 128 + t] * v[t];
    #pragma unroll
    for (int o = 16; o; o >>= 1) s += __shfl_xor_sync(0xffffffffu, s, o);
    __shared__ float ws[4];
    if ((t & 31) == 0) ws[t >> 5] = s;
    __syncthreads();
    if (t == 0) y[r] = ws[0] + ws[1] + ws[2] + ws[3];
}

__global__ void wvec_kernel(const float* __restrict__ W3, const float* __restrict__ a3,
                            float* __restrict__ out3) {
    int i = blockIdx.x, k = threadIdx.x;
    __shared__ float sa[128];
    sa[k] = a3[i * 128 + k];
    __syncthreads();
    const float* W = W3 + (size_t)i * 16384 + (size_t)k * 128;
    float s = 0.f;
    #pragma unroll 8
    for (int c = 0; c < 128; c++) s += W[c] * sa[c];
    out3[i * 128 + k] = s;
}

__global__ void maxred_kernel(const float* __restrict__ a, int n, float* __restrict__ out) {
    int t = threadIdx.x;
    float m = -3.0e38f;
    for (int i = t; i < n; i += 256) m = fmaxf(m, a[i]);
    #pragma unroll
    for (int o = 16; o; o >>= 1) m = fmaxf(m, __shfl_xor_sync(0xffffffffu, m, o));
    __shared__ float ws[8];
    if ((t & 31) == 0) ws[t >> 5] = m;
    __syncthreads();
    if (t == 0) {
        float mm = ws[0];
        #pragma unroll
        for (int i = 1; i < 8; i++) mm = fmaxf(mm, ws[i]);
        out[0] = mm;
    }
}

// C = A@W (+bias) (+C) (relu); tile 64x128, 256 thr
__global__ __launch_bounds__(256) void linear_kernel(
    const float* __restrict__ A, const float* __restrict__ W,
    const float* __restrict__ bias, float* __restrict__ C,
    int M, int K, int N, int addC, int doRelu)
{
    __shared__ float As[16][64];
    __shared__ float Ws[16][128];
    int rb = blockIdx.x * 64, cb = blockIdx.y * 128;
    int t = threadIdx.x, cg = t & 31, rg = t >> 5;
    float acc[8][4];
    #pragma unroll
    for (int i = 0; i < 8; i++)
        #pragma unroll
        for (int j = 0; j < 4; j++) acc[i][j] = 0.f;
    for (int k0 = 0; k0 < K; k0 += 16) {
        for (int i = t; i < 1024; i += 256) {
            int r = i >> 4, kk = i & 15, kg = k0 + kk;
            As[kk][r] = (kg < K) ? A[(size_t)(rb + r) * K + kg] : 0.f;
        }
        for (int i = t; i < 2048; i += 256) {
            int kk = i >> 7, c = i & 127, kg = k0 + kk;
            Ws[kk][c] = (kg < K && (cb + c) < N) ? W[(size_t)kg * N + cb + c] : 0.f;
        }
        __syncthreads();
        #pragma unroll
        for (int kk = 0; kk < 16; kk++) {
            float4 w4 = *(float4*)&Ws[kk][cg * 4];
            #pragma unroll
            for (int i = 0; i < 8; i++) {
                float a = As[kk][rg * 8 + i];
                acc[i][0] += a * w4.x; acc[i][1] += a * w4.y;
                acc[i][2] += a * w4.z; acc[i][3] += a * w4.w;
            }
        }
        __syncthreads();
    }
    #pragma unroll
    for (int i = 0; i < 8; i++) {
        int row = rb + rg * 8 + i;
        if (row >= M) continue;
        #pragma unroll
        for (int j = 0; j < 4; j++) {
            int col = cb + cg * 4 + j;
            if (col < N) {
                float v = acc[i][j];
                if (bias) v += bias[col];
                if (addC) v += C[(size_t)row * N + col];
                if (doRelu) v = fmaxf(v, 0.f);
                C[(size_t)row * N + col] = v;
            }
        }
    }
}

// fused hetero GAT, f32x2 math. grid 448 = 7 combos x 64 author blocks.
__global__ __launch_bounds__(256, 2) void hetero_kernel(
    const float* __restrict__ an, const float* __restrict__ ald3,
    const float* __restrict__ mxs,
    const float* __restrict__ snp, const float* __restrict__ gp, const float* __restrict__ alsp,
    const float* __restrict__ snt, const float* __restrict__ gt, const float* __restrict__ alst,
    const float* __restrict__ snc, const float* __restrict__ gc, const float* __restrict__ alsc,
    float* __restrict__ acc, float* __restrict__ deng)
{
    extern __shared__ char smraw[];
    float* sAN  = (float*)smraw;             // 64x128 f  (32768B)
    ull*   sB2  = (ull*)(smraw + 32768);     // 64x34 ull (17408B) k-pair-packed SN^T
    float* sHS  = (float*)(smraw + 50176);   // 32x128 f  (16384B)
    ull*   sW2  = (ull*)(smraw + 66560);     // 64x33 ull (16896B)
    float* sALD = (float*)(smraw + 83456);   // 64
    float* sDEN = (float*)(smraw + 83712);   // 64
    float* sALS = (float*)(smraw + 83968);   // 32
    ull* sANu = (ull*)sAN;
    ull* sHSu = (ull*)sHS;

    int bx = blockIdx.x, combo = bx >> 6, ab = bx & 63;
    int type, seg0;
    const float *sn, *hs, *als;
    if (combo < 4)      { type = 0; seg0 = combo << 11;       sn = snp; hs = gp; als = alsp; }
    else if (combo < 6) { type = 1; seg0 = (combo - 4) << 11; sn = snt; hs = gt; als = alst; }
    else                { type = 2; seg0 = 0;                 sn = snc; hs = gc; als = alsc; }

    int t = threadIdx.x, cg = t & 15, rg = t >> 4;
    int r0g = ab << 6;
    float mx = mxs[type];

    for (int i = t; i < 2048; i += 256) {
        int r = i >> 5, q = i & 31;
        *(float4*)&sAN[r * 128 + q * 4] =
            *(const float4*)&an[(size_t)(r0g + r) * 128 + q * 4];
    }
    if (t < 64) { sALD[t] = ald3[type * NA + r0g + t]; sDEN[t] = 0.f; }

    ull num2[4][4];
    #pragma unroll
    for (int i = 0; i < 4; i++)
        #pragma unroll
        for (int p = 0; p < 4; p++) num2[i][p] = 0ull;
    __syncthreads();

    for (int ch = 0; ch < 64; ch++) {
        int j0 = seg0 + (ch << 5);
        for (int i = t; i < 1024; i += 256) {
            int j = i >> 5, q = i & 31;
            float4 v = *(const float4*)&sn[(size_t)(j0 + j) * 128 + q * 4];
            sB2[(2 * q) * 34 + j]     = pack2(v.x, v.y);
            sB2[(2 * q + 1) * 34 + j] = pack2(v.z, v.w);
            *(float4*)&sHS[j * 128 + q * 4] =
                *(const float4*)&hs[(size_t)(j0 + j) * 128 + q * 4];
        }
        if (t < 32) sALS[t] = als[j0 + t];
        __syncthreads();

        // phase 1: packed-k dot products
        ull S2[4][2];
        #pragma unroll
        for (int i = 0; i < 4; i++) { S2[i][0] = 0ull; S2[i][1] = 0ull; }
        #pragma unroll 4
        for (int q = 0; q < 32; q++) {
            ulonglong2 b0 = *(ulonglong2*)&sB2[(2 * q) * 34 + cg * 2];
            ulonglong2 b1 = *(ulonglong2*)&sB2[(2 * q + 1) * 34 + cg * 2];
            #pragma unroll
            for (int i = 0; i < 4; i++) {
                ulonglong2 a = *(ulonglong2*)&sANu[(rg * 4 + i) * 64 + 2 * q];
                fma2(S2[i][0], a.x, b0.x); fma2(S2[i][1], a.x, b0.y);
                fma2(S2[i][0], a.y, b1.x); fma2(S2[i][1], a.y, b1.y);
            }
        }

        // phase 1.5: weights + denominators
        float rsum[4];
        #pragma unroll
        for (int i = 0; i < 4; i++) {
            float aldr = sALD[rg * 4 + i];
            float tm = aldr + mx;
            float mrow = tm >= 0.f ? tm : 0.2f * tm;
            rsum[i] = 0.f;
            #pragma unroll
            for (int jj = 0; jj < 2; jj++) {
                float2 sp = unpack2(S2[i][jj]);
                float sval = sp.x + sp.y;
                float w = 0.f;
                int jgl = j0 + cg * 2 + jj;
                if (sval > 0.1f && (r0g + rg * 4 + i) != jgl) {
                    float e0 = aldr + sALS[cg * 2 + jj];
                    float e = e0 >= 0.f ? e0 : 0.2f * e0;
                    w = __expf(e - mrow);
                }
                sW2[(rg * 4 + i) * 33 + cg * 2 + jj] = pack2(w, w);
                rsum[i] += w;
            }
        }
        #pragma unroll
        for (int o = 1; o < 16; o <<= 1)
            #pragma unroll
            for (int i = 0; i < 4; i++)
                rsum[i] += __shfl_xor_sync(0xffffffffu, rsum[i], o);
        if (cg == 0)
            #pragma unroll
            for (int i = 0; i < 4; i++) sDEN[rg * 4 + i] += rsum[i];
        __syncthreads();

        // phase 2: num += W @ HS, packed columns
        #pragma unroll 2
        for (int j = 0; j < 32; j++) {
            ulonglong2 hA = *(ulonglong2*)&sHSu[j * 64 + cg * 2];
            ulonglong2 hB = *(ulonglong2*)&sHSu[j * 64 + 32 + cg * 2];
            #pragma unroll
            for (int i = 0; i < 4; i++) {
                ull wp = sW2[(rg * 4 + i) * 33 + j];
                fma2(num2[i][0], wp, hA.x); fma2(num2[i][1], wp, hA.y);
                fma2(num2[i][2], wp, hB.x); fma2(num2[i][3], wp, hB.y);
            }
        }
        __syncthreads();
    }

    float* accT = acc + (size_t)type * NA * 128;
    #pragma unroll
    for (int i = 0; i < 4; i++) {
        size_t row = (size_t)(r0g + rg * 4 + i) * 128;
        float2 v0 = unpack2(num2[i][0]), v1 = unpack2(num2[i][1]);
        float2 v2 = unpack2(num2[i][2]), v3 = unpack2(num2[i][3]);
        size_t b1 = row + cg * 4, b2 = row + 64 + cg * 4;
        atomicAdd(&accT[b1 + 0], v0.x); atomicAdd(&accT[b1 + 1], v0.y);
        atomicAdd(&accT[b1 + 2], v1.x); atomicAdd(&accT[b1 + 3], v1.y);
        atomicAdd(&accT[b2 + 0], v2.x); atomicAdd(&accT[b2 + 1], v2.y);
        atomicAdd(&accT[b2 + 2], v3.x); atomicAdd(&accT[b2 + 3], v3.y);
    }
    if (cg == 0)
        #pragma unroll
        for (int i = 0; i < 4; i++)
            atomicAdd(&deng[type * NA + r0g + rg * 4 + i], sDEN[rg * 4 + i]);
}

__global__ void finalize_kernel(float* __restrict__ acc, const float* __restrict__ den,
                                const float* __restrict__ gb) {
    int idx = blockIdx.x * blockDim.x + threadIdx.x;
    if (idx >= 3 * NA * 128) return;
    int c = idx & 127, dr = idx >> 7, type = idx >> 19;
    float d = den[dr], b = gb[type * 128 + c];
    acc[idx] = (d > 0.f) ? acc[idx] / d + b : b;
}

__global__ void attscore_kernel(const float* __restrict__ heter, const float* __restrict__ xt,
                                const float* __restrict__ Watt, const float* __restrict__ atts,
                                float* __restrict__ ssum) {
    int set = blockIdx.y;
    const float* X = (set < 3) ? heter + (size_t)set * NA * 128 : xt;
    int rb = blockIdx.x * 4, t = threadIdx.x, c = t & 63;
    __shared__ float xs[4][128];
    for (int i = t; i < 512; i += 256)
        xs[i >> 7][i & 127] = X[(size_t)(rb + (i >> 7)) * 128 + (i & 127)];
    __syncthreads();
    const float* xr = xs[t >> 6];
    float dot = 0.f;
    #pragma unroll 8
    for (int k = 0; k < 128; k++) dot += xr[k] * Watt[k * 64 + c];
    float val = (1.f / (1.f + __expf(-dot))) * atts[set * 64 + c];
    #pragma unroll
    for (int o = 16; o; o >>= 1) val += __shfl_xor_sync(0xffffffffu, val, o);
    __shared__ float ps[8];
    if ((t & 31) == 0) ps[t >> 5] = val;
    __syncthreads();
    if (t == 0) {
        float s = 0.f;
        #pragma unroll
        for (int i = 0; i < 8; i++) s += ps[i];
        atomicAdd(&ssum[set], s);
    }
}

__global__ void alpha_kernel(const float* __restrict__ ssum, float* __restrict__ alpha) {
    if (threadIdx.x == 0) {
        float s[4], m = -3e38f;
        for (int i = 0; i < 4; i++) { s[i] = ssum[i] / (float)NA; m = fmaxf(m, s[i]); }
        float e[4], tot = 0.f;
        for (int i = 0; i < 4; i++) { e[i] = expf(s[i] - m); tot += e[i]; }
        for (int i = 0; i < 4; i++) alpha[i] = e[i] / tot;
    }
}

__global__ void xatt_kernel(const float* __restrict__ heter, const float* __restrict__ xt,
                            const float* __restrict__ alpha, float* __restrict__ out) {
    int idx = blockIdx.x * blockDim.x + threadIdx.x;
    if (idx >= NA * 128) return;
    out[idx] = alpha[0] * heter[idx] + alpha[1] * heter[NA * 128 + idx] +
               alpha[2] * heter[2 * NA * 128 + idx] + alpha[3] * xt[idx];
}

__global__ void deg_kernel(const int* __restrict__ dst, float* __restrict__ deg, int E) {
    int e = blockIdx.x * blockDim.x + threadIdx.x;
    if (e < E) atomicAdd(&deg[dst[e]], 1.0f);
}

__global__ void scatter_kernel(const float* __restrict__ X, const int* __restrict__ src,
                               const int* __restrict__ dst, float* __restrict__ AGG,
                               int E, int C) {
    int idx = blockIdx.x * blockDim.x + threadIdx.x;
    int per = C >> 2;
    if (idx >= E * per) return;
    int e = idx / per, q = idx - e * per;
    int s = src[e], d = dst[e];
    float4 v = *(const float4*)&X[(size_t)s * C + q * 4];
    float* o = &AGG[(size_t)d * C + q * 4];
    atomicAdd(o + 0, v.x); atomicAdd(o + 1, v.y);
    atomicAdd(o + 2, v.z); atomicAdd(o + 3, v.w);
}

__global__ void rowdiv_kernel(float* __restrict__ AGG, const float* __restrict__ deg,
                              int n, int C) {
    int idx = blockIdx.x * blockDim.x + threadIdx.x;
    if (idx >= n) return;
    AGG[idx] = AGG[idx] / fmaxf(deg[idx / C], 1.0f);
}

extern "C" void kernel_launch(void* const* d_in, const int* in_sizes, int n_in,
                              void* d_out, int out_size) {
    const float* x_ma = (const float*)d_in[0];
    const float* x_mp = (const float*)d_in[1];
    const float* x_mt = (const float*)d_in[2];
    const float* x_mc = (const float*)d_in[3];
    const float* x_ia = (const float*)d_in[4];
    const int*   edge = (const int*)d_in[5];
    const float* Wla  = (const float*)d_in[6];  const float* bla  = (const float*)d_in[7];
    const float* Wlp  = (const float*)d_in[8];  const float* blp  = (const float*)d_in[9];
    const float* Wlt  = (const float*)d_in[10]; const float* blt  = (const float*)d_in[11];
    const float* Wlc  = (const float*)d_in[12]; const float* blc  = (const float*)d_in[13];
    const float* Wltg = (const float*)d_in[14]; const float* bltg = (const float*)d_in[15];
    const float* gWs  = (const float*)d_in[16];
    const float* gWd  = (const float*)d_in[17];
    const float* gas  = (const float*)d_in[18];
    const float* gad  = (const float*)d_in[19];
    const float* gb   = (const float*)d_in[20];
    const float* Watt = (const float*)d_in[21];
    const float* atts = (const float*)d_in[22];
    const float* W1l  = (const float*)d_in[23]; const float* b1 = (const float*)d_in[24];
    const float* W1r  = (const float*)d_in[25];
    const float* W2l  = (const float*)d_in[26]; const float* b2 = (const float*)d_in[27];
    const float* W2r  = (const float*)d_in[28];

    int E = in_sizes[5] / 2;
    int Ka = in_sizes[0] / NA, Kp = in_sizes[1] / NP, Kt = in_sizes[2] / NT;
    int Kc = in_sizes[3] / NC, Kg = in_sizes[4] / NA;

    float* out_x   = (float*)d_out;
    float* out_att = (float*)d_out + (size_t)NA * 64;

    float *ha,*hp,*ht,*hc,*xt,*an,*snp,*snt,*snc,*gp,*gt,*gc;
    float *alsp,*alst,*alsc,*ald,*wdv,*mxs,*acc,*den,*ssum,*alpha,*agg1,*deg,*h1,*q,*aggq;
    cudaGetSymbolAddress((void**)&ha,g_ha);   cudaGetSymbolAddress((void**)&hp,g_hp);
    cudaGetSymbolAddress((void**)&ht,g_ht);   cudaGetSymbolAddress((void**)&hc,g_hc);
    cudaGetSymbolAddress((void**)&xt,g_xt);   cudaGetSymbolAddress((void**)&an,g_an);
    cudaGetSymbolAddress((void**)&snp,g_snp); cudaGetSymbolAddress((void**)&snt,g_snt);
    cudaGetSymbolAddress((void**)&snc,g_snc); cudaGetSymbolAddress((void**)&gp,g_gp);
    cudaGetSymbolAddress((void**)&gt,g_gt);   cudaGetSymbolAddress((void**)&gc,g_gc);
    cudaGetSymbolAddress((void**)&alsp,g_alsp); cudaGetSymbolAddress((void**)&alst,g_alst);
    cudaGetSymbolAddress((void**)&alsc,g_alsc); cudaGetSymbolAddress((void**)&ald,g_ald);
    cudaGetSymbolAddress((void**)&wdv,g_wdv);  cudaGetSymbolAddress((void**)&mxs,g_mxs);
    cudaGetSymbolAddress((void**)&acc,g_acc);  cudaGetSymbolAddress((void**)&den,g_den);
    cudaGetSymbolAddress((void**)&ssum,g_ssum);cudaGetSymbolAddress((void**)&alpha,g_alpha);
    cudaGetSymbolAddress((void**)&agg1,g_agg1);cudaGetSymbolAddress((void**)&deg,g_deg);
    cudaGetSymbolAddress((void**)&h1,g_h1);    cudaGetSymbolAddress((void**)&q,g_q);
    cudaGetSymbolAddress((void**)&aggq,g_aggq);

    dim3 blk(256);
    linear_kernel<<<dim3(NA/64,1),blk>>>(x_ma, Wla,  bla,  ha, NA, Ka, 128, 0, 0);
    linear_kernel<<<dim3(NP/64,1),blk>>>(x_mp, Wlp,  blp,  hp, NP, Kp, 128, 0, 0);
    linear_kernel<<<dim3(NT/64,1),blk>>>(x_mt, Wlt,  blt,  ht, NT, Kt, 128, 0, 0);
    linear_kernel<<<dim3(NC/64,1),blk>>>(x_mc, Wlc,  blc,  hc, NC, Kc, 128, 0, 0);
    linear_kernel<<<dim3(NA/64,1),blk>>>(x_ia, Wltg, bltg, xt, NA, Kg, 128, 0, 0);
    linear_kernel<<<dim3(NP/64,1),blk>>>(hp, gWs + 0*16384, nullptr, gp, NP, 128, 128, 0, 0);
    linear_kernel<<<dim3(NT/64,1),blk>>>(ht, gWs + 1*16384, nullptr, gt, NT, 128, 128, 0, 0);
    linear_kernel<<<dim3(NC/64,1),blk>>>(hc, gWs + 2*16384, nullptr, gc, NC, 128, 128, 0, 0);
    rownorm_kernel<<<NA,128>>>(ha, an);
    rownorm_kernel<<<NP,128>>>(hp, snp);
    rownorm_kernel<<<NT,128>>>(ht, snt);
    rownorm_kernel<<<NC,128>>>(hc, snc);
    wvec_kernel<<<3,128>>>(gWd, gad, wdv);
    matvec_kernel<<<NA,128>>>(ha, wdv + 0,   ald + 0*NA);
    matvec_kernel<<<NA,128>>>(ha, wdv + 128, ald + 1*NA);
    matvec_kernel<<<NA,128>>>(ha, wdv + 256, ald + 2*NA);
    matvec_kernel<<<NP,128>>>(gp, gas + 0,   alsp);
    matvec_kernel<<<NT,128>>>(gt, gas + 128, alst);
    matvec_kernel<<<NC,128>>>(gc, gas + 256, alsc);
    maxred_kernel<<<1,256>>>(alsp, NP, mxs + 0);
    maxred_kernel<<<1,256>>>(alst, NT, mxs + 1);
    maxred_kernel<<<1,256>>>(alsc, NC, mxs + 2);
    zero_kernel<<<(3*NA*128)/256,256>>>(acc, 3*NA*128);
    zero_kernel<<<(3*NA+255)/256,256>>>(den, 3*NA);
    zero_kernel<<<1,32>>>(ssum, 4);
    zero_kernel<<<(NA*128)/256,256>>>(agg1, NA*128);
    zero_kernel<<<(NA+255)/256,256>>>(deg, NA);
    zero_kernel<<<(NA*64)/256,256>>>(aggq, NA*64);
    cudaFuncSetAttribute(hetero_kernel, cudaFuncAttributeMaxDynamicSharedMemorySize, 84096);
    hetero_kernel<<<448,256,84096>>>(an, ald, mxs, snp, gp, alsp,
                                     snt, gt, alst, snc, gc, alsc, acc, den);
    finalize_kernel<<<(3*NA*128)/256,256>>>(acc, den, gb);
    attscore_kernel<<<dim3(NA/4,4),256>>>(acc, xt, Watt, atts, ssum);
    alpha_kernel<<<1,32>>>(ssum, alpha);
    xatt_kernel<<<(NA*128)/256,256>>>(acc, xt, alpha, out_att);
    // GraphSAGE
    deg_kernel<<<(E+255)/256,256>>>(edge + E, deg, E);
    scatter_kernel<<<(E*32)/256,256>>>(ha, edge, edge + E, agg1, E, 128);
    rowdiv_kernel<<<(NA*128)/256,256>>>(agg1, deg, NA*128, 128);
    linear_kernel<<<dim3(NA/64,2),blk>>>(agg1, W1l, b1,      h1, NA, 128, 256, 0, 0);
    linear_kernel<<<dim3(NA/64,2),blk>>>(ha,   W1r, nullptr, h1, NA, 128, 256, 1, 1);
    // layer 2: project-then-scatter (exact by linearity of segment_sum)
    linear_kernel<<<dim3(NA/64,1),blk>>>(h1, W2l, nullptr, q, NA, 256, 64, 0, 0);
    scatter_kernel<<<(E*16)/256,256>>>(q, edge, edge + E, aggq, E, 64);
    cudaMemcpyAsync(out_x, aggq, (size_t)NA*64*sizeof(float), cudaMemcpyDeviceToDevice);
    rowdiv_kernel<<<(NA*64)/256,256>>>(out_x, deg, NA*64, 64);
    linear_kernel<<<dim3(NA/64,1),blk>>>(h1, W2r, b2, out_x, NA, 256, 64, 1, 0);
}

// round 5
// speedup vs baseline: 1.5275x; 1.2756x over previous
#include <cuda_runtime.h>
#include <math.h>

#define NA 4096
#define NP 8192
#define NT 4096
#define NC 2048
typedef unsigned long long ull;

__device__ float g_ha[NA*128];
__device__ float g_hp[NP*128];
__device__ float g_ht[NT*128];
__device__ float g_hc[NC*128];
__device__ float g_xt[NA*128];
__device__ float g_an[NA*128];
__device__ float g_snp[NP*128];
__device__ float g_snt[NT*128];
__device__ float g_snc[NC*128];
__device__ float g_gp[NP*128];
__device__ float g_gt[NT*128];
__device__ float g_gc[NC*128];
__device__ float g_alsp[NP];
__device__ float g_alst[NT];
__device__ float g_alsc[NC];
__device__ float g_ald[3*NA];
__device__ float g_wdv[3*128];
__device__ unsigned g_mxsEnc[3];
__device__ float g_acc[3*NA*128];
__device__ float g_den[3*NA];
__device__ float g_ssum[4];
__device__ float g_alpha[4];
__device__ float g_agg1[NA*128];
__device__ float g_deg[NA];
__device__ float g_h1[NA*256];
__device__ float g_q[NA*64];
__device__ float g_aggq[NA*64];

__device__ __forceinline__ void fma2(ull& d, ull a, ull b) {
    asm("fma.rn.f32x2 %0, %1, %2, %0;" : "+l"(d) : "l"(a), "l"(b));
}
__device__ __forceinline__ ull pack2(float x, float y) {
    ull r; asm("mov.b64 %0, {%1, %2};" : "=l"(r) : "f"(x), "f"(y)); return r;
}
__device__ __forceinline__ float2 unpack2(ull v) {
    float2 r; asm("mov.b64 {%0, %1}, %2;" : "=f"(r.x), "=f"(r.y) : "l"(v)); return r;
}
__device__ __forceinline__ unsigned enc_f(float f) {
    unsigned b = __float_as_uint(f);
    return (b & 0x80000000u) ? ~b : (b | 0x80000000u);
}
__device__ __forceinline__ float dec_f(unsigned u) {
    unsigned b = (u & 0x80000000u) ? (u ^ 0x80000000u) : ~u;
    return __uint_as_float(b);
}

// ---------- fused zero init ----------
__global__ void zero_all(float* __restrict__ acc, float* __restrict__ agg1,
                         float* __restrict__ aggq, float* __restrict__ den,
                         float* __restrict__ deg, float* __restrict__ ssum,
                         unsigned* __restrict__ mxsEnc) {
    int i = blockIdx.x * 256 + threadIdx.x;
    if (i < 1572864) { acc[i] = 0.f; return; }
    i -= 1572864; if (i < 524288) { agg1[i] = 0.f; return; }
    i -= 524288;  if (i < 262144) { aggq[i] = 0.f; return; }
    i -= 262144;  if (i < 12288)  { den[i] = 0.f; return; }
    i -= 12288;   if (i < 4096)   { deg[i] = 0.f; return; }
    i -= 4096;    if (i < 4)      { ssum[i] = 0.f; return; }
    i -= 4;       if (i < 3)      mxsEnc[i] = enc_f(-3.0e38f);
}

// ---------- wdv[i][k] = sum_c gWd[i][k][c]*gad[i][c] ----------
__global__ void wvec_kernel(const float* __restrict__ W3, const float* __restrict__ a3,
                            float* __restrict__ out3) {
    int i = blockIdx.x, k = threadIdx.x;
    __shared__ float sa[128];
    sa[k] = a3[i * 128 + k];
    __syncthreads();
    const float* W = W3 + (size_t)i * 16384 + (size_t)k * 128;
    float s = 0.f;
    #pragma unroll 8
    for (int c = 0; c < 128; c++) s += W[c] * sa[c];
    out3[i * 128 + k] = s;
}

// ---------- batched linear ----------
struct LJob {
    const float *A, *W, *A2, *W2, *bias, *addD, *degp;
    float* C;
    int M, K, K2, N, relu, colBlks, blkStart;
};
struct LJobs { LJob j[5]; int n; };

__global__ __launch_bounds__(256) void lin_batch(LJobs P) {
    int bid = blockIdx.x;
    int sel = 0;
    #pragma unroll
    for (int i = 1; i < 5; i++)
        if (i < P.n && bid >= P.j[i].blkStart) sel = i;
    LJob J = P.j[sel];
    int rel = bid - J.blkStart;
    int rb = (rel / J.colBlks) * 64, cb = (rel % J.colBlks) * 128;

    __shared__ float As[16][64];
    __shared__ float Ws[16][128];
    int t = threadIdx.x, cg = t & 31, rg = t >> 5;
    float acc[8][4];
    #pragma unroll
    for (int i = 0; i < 8; i++)
        #pragma unroll
        for (int j = 0; j < 4; j++) acc[i][j] = 0.f;

    #pragma unroll 1
    for (int ph = 0; ph < 2; ph++) {
        const float* A = ph ? J.A2 : J.A;
        const float* W = ph ? J.W2 : J.W;
        int K = ph ? J.K2 : J.K;
        if (!A) break;
        for (int k0 = 0; k0 < K; k0 += 16) {
            for (int i = t; i < 1024; i += 256) {
                int r = i >> 4, kk = i & 15, kg = k0 + kk;
                As[kk][r] = (kg < K) ? A[(size_t)(rb + r) * K + kg] : 0.f;
            }
            for (int i = t; i < 2048; i += 256) {
                int kk = i >> 7, c = i & 127, kg = k0 + kk;
                Ws[kk][c] = (kg < K && (cb + c) < J.N) ? W[(size_t)kg * J.N + cb + c] : 0.f;
            }
            __syncthreads();
            #pragma unroll
            for (int kk = 0; kk < 16; kk++) {
                float4 w4 = *(float4*)&Ws[kk][cg * 4];
                #pragma unroll
                for (int i = 0; i < 8; i++) {
                    float a = As[kk][rg * 8 + i];
                    acc[i][0] += a * w4.x; acc[i][1] += a * w4.y;
                    acc[i][2] += a * w4.z; acc[i][3] += a * w4.w;
                }
            }
            __syncthreads();
        }
    }
    #pragma unroll
    for (int i = 0; i < 8; i++) {
        int row = rb + rg * 8 + i;
        float dscale = J.degp ? 1.f / fmaxf(J.degp[row], 1.f) : 1.f;
        #pragma unroll
        for (int j = 0; j < 4; j++) {
            int col = cb + cg * 4 + j;
            if (col < J.N) {
                float v = acc[i][j];
                if (J.bias) v += J.bias[col];
                if (J.addD) v += J.addD[(size_t)row * J.N + col] * dscale;
                if (J.relu) v = fmaxf(v, 0.f);
                J.C[(size_t)row * J.N + col] = v;
            }
        }
    }
}

// ---------- fused prep: rownorms + matvecs(+max) ----------
__global__ void prep_all(
    const float* __restrict__ ha, const float* __restrict__ hp,
    const float* __restrict__ ht, const float* __restrict__ hc,
    float* __restrict__ an, float* __restrict__ snp,
    float* __restrict__ snt, float* __restrict__ snc,
    const float* __restrict__ gp, const float* __restrict__ gt, const float* __restrict__ gc,
    const float* __restrict__ wdv, const float* __restrict__ gas,
    float* __restrict__ ald, float* __restrict__ alsp, float* __restrict__ alst,
    float* __restrict__ alsc, unsigned* __restrict__ mxsEnc)
{
    int m = blockIdx.x, t = threadIdx.x;
    __shared__ float ws[4];
    if (m < 18432) {
        const float* X; float* Y; int r;
        if (m < 4096)       { X = ha; Y = an;  r = m; }
        else if (m < 12288) { X = hp; Y = snp; r = m - 4096; }
        else if (m < 16384) { X = ht; Y = snt; r = m - 12288; }
        else                { X = hc; Y = snc; r = m - 16384; }
        float v = X[(size_t)r * 128 + t];
        float s = v * v;
        #pragma unroll
        for (int o = 16; o; o >>= 1) s += __shfl_xor_sync(0xffffffffu, s, o);
        if ((t & 31) == 0) ws[t >> 5] = s;
        __syncthreads();
        float tot = ws[0] + ws[1] + ws[2] + ws[3];
        Y[(size_t)r * 128 + t] = v / fmaxf(sqrtf(tot), 1e-12f);
    } else {
        int m2 = m - 18432;
        const float* X; const float* vec; float* y; int r; int mxi = -1;
        if (m2 < 12288) {
            int tpe = m2 >> 12;
            X = ha; vec = wdv + tpe * 128; y = ald + tpe * NA; r = m2 & 4095;
        } else {
            int m3 = m2 - 12288;
            if (m3 < 8192)       { X = gp; vec = gas;       y = alsp; r = m3;         mxi = 0; }
            else if (m3 < 12288) { X = gt; vec = gas + 128; y = alst; r = m3 - 8192;  mxi = 1; }
            else                 { X = gc; vec = gas + 256; y = alsc; r = m3 - 12288; mxi = 2; }
        }
        float s = X[(size_t)r * 128 + t] * vec[t];
        #pragma unroll
        for (int o = 16; o; o >>= 1) s += __shfl_xor_sync(0xffffffffu, s, o);
        if ((t & 31) == 0) ws[t >> 5] = s;
        __syncthreads();
        if (t == 0) {
            float tot = ws[0] + ws[1] + ws[2] + ws[3];
            y[r] = tot;
            if (mxi >= 0) atomicMax(&mxsEnc[mxi], enc_f(tot));
        }
    }
}

// ---------- hetero flush ----------
__device__ __forceinline__ void hetero_flush(
    float* __restrict__ acc, float* __restrict__ deng, const float* __restrict__ sDEN,
    ull (&num2)[4][4], int curType, int r0g, int rg, int cg)
{
    float* accT = acc + (size_t)curType * NA * 128;
    #pragma unroll
    for (int i = 0; i < 4; i++) {
        size_t row = (size_t)(r0g + rg * 4 + i) * 128;
        float2 v0 = unpack2(num2[i][0]), v1 = unpack2(num2[i][1]);
        float2 v2 = unpack2(num2[i][2]), v3 = unpack2(num2[i][3]);
        size_t b1 = row + cg * 4, b2 = row + 64 + cg * 4;
        atomicAdd(&accT[b1 + 0], v0.x); atomicAdd(&accT[b1 + 1], v0.y);
        atomicAdd(&accT[b1 + 2], v1.x); atomicAdd(&accT[b1 + 3], v1.y);
        atomicAdd(&accT[b2 + 0], v2.x); atomicAdd(&accT[b2 + 1], v2.y);
        atomicAdd(&accT[b2 + 2], v3.x); atomicAdd(&accT[b2 + 3], v3.y);
    }
    if (cg == 0) {
        #pragma unroll
        for (int i = 0; i < 4; i++)
            atomicAdd(&deng[curType * NA + r0g + rg * 4 + i], sDEN[rg * 4 + i]);
    }
}

// ---------- persistent fused hetero GAT (f32x2), grid = 304 balanced ----------
#define HET_GRID 304
__global__ __launch_bounds__(256, 2) void hetero_kernel(
    const float* __restrict__ an, const float* __restrict__ ald3,
    const unsigned* __restrict__ mxsEnc,
    const float* __restrict__ snp, const float* __restrict__ gp, const float* __restrict__ alsp,
    const float* __restrict__ snt, const float* __restrict__ gt, const float* __restrict__ alst,
    const float* __restrict__ snc, const float* __restrict__ gc, const float* __restrict__ alsc,
    float* __restrict__ acc, float* __restrict__ deng)
{
    extern __shared__ char smraw[];
    float* sAN  = (float*)smraw;             // 64x128 f  (32768B)
    ull*   sB2  = (ull*)(smraw + 32768);     // 64x34 ull (17408B)
    float* sHS  = (float*)(smraw + 50176);   // 32x128 f  (16384B)
    ull*   sW2  = (ull*)(smraw + 66560);     // 64x33 ull (16896B)
    float* sALD = (float*)(smraw + 83456);
    float* sDEN = (float*)(smraw + 83712);
    float* sALS = (float*)(smraw + 83968);
    ull* sANu = (ull*)sAN;
    ull* sHSu = (ull*)sHS;

    const int TOT = 28672;
    int bid = blockIdx.x;
    int cs = (int)(((long long)bid * TOT) / HET_GRID);
    int ce = (int)(((long long)(bid + 1) * TOT) / HET_GRID);
    int t = threadIdx.x, cg = t & 15, rg = t >> 4;

    int curType = -1, curAb = -1, r0g = 0;
    float mx = 0.f;
    const float *sn = snp, *hs = gp, *als = alsp;
    ull num2[4][4];

    for (int c = cs; c < ce; c++) {
        int type, ab, ch;
        if (c < 16384)      { type = 0; ab = c >> 8; ch = c & 255; }
        else if (c < 24576) { int c2 = c - 16384; type = 1; ab = c2 >> 7; ch = c2 & 127; }
        else                { int c2 = c - 24576; type = 2; ab = c2 >> 6; ch = c2 & 63; }
        int j0 = ch << 5;

        if (type != curType || ab != curAb) {
            if (curType >= 0) {
                hetero_flush(acc, deng, sDEN, num2, curType, r0g, rg, cg);
                __syncthreads();
            }
            curType = type; curAb = ab; r0g = ab << 6;
            if (type == 0)      { sn = snp; hs = gp; als = alsp; }
            else if (type == 1) { sn = snt; hs = gt; als = alst; }
            else                { sn = snc; hs = gc; als = alsc; }
            mx = dec_f(mxsEnc[type]);
            for (int i = t; i < 2048; i += 256) {
                int r = i >> 5, q = i & 31;
                *(float4*)&sAN[r * 128 + q * 4] =
                    *(const float4*)&an[(size_t)(r0g + r) * 128 + q * 4];
            }
            if (t < 64) { sALD[t] = ald3[type * NA + r0g + t]; sDEN[t] = 0.f; }
            #pragma unroll
            for (int i = 0; i < 4; i++)
                #pragma unroll
                for (int p = 0; p < 4; p++) num2[i][p] = 0ull;
            __syncthreads();
        }

        // load SN (k-pair packed) + HS chunk
        for (int i = t; i < 1024; i += 256) {
            int j = i >> 5, q = i & 31;
            float4 v = *(const float4*)&sn[(size_t)(j0 + j) * 128 + q * 4];
            sB2[(2 * q) * 34 + j]     = pack2(v.x, v.y);
            sB2[(2 * q + 1) * 34 + j] = pack2(v.z, v.w);
            *(float4*)&sHS[j * 128 + q * 4] =
                *(const float4*)&hs[(size_t)(j0 + j) * 128 + q * 4];
        }
        if (t < 32) sALS[t] = als[j0 + t];
        __syncthreads();

        // phase 1: packed-k dot products
        ull S2[4][2];
        #pragma unroll
        for (int i = 0; i < 4; i++) { S2[i][0] = 0ull; S2[i][1] = 0ull; }
        #pragma unroll 4
        for (int q = 0; q < 32; q++) {
            ulonglong2 b0 = *(ulonglong2*)&sB2[(2 * q) * 34 + cg * 2];
            ulonglong2 b1 = *(ulonglong2*)&sB2[(2 * q + 1) * 34 + cg * 2];
            #pragma unroll
            for (int i = 0; i < 4; i++) {
                ulonglong2 a = *(ulonglong2*)&sANu[(rg * 4 + i) * 64 + 2 * q];
                fma2(S2[i][0], a.x, b0.x); fma2(S2[i][1], a.x, b0.y);
                fma2(S2[i][0], a.y, b1.x); fma2(S2[i][1], a.y, b1.y);
            }
        }

        // phase 1.5: weights + denominators
        float rsum[4];
        #pragma unroll
        for (int i = 0; i < 4; i++) {
            float aldr = sALD[rg * 4 + i];
            float tm = aldr + mx;
            float mrow = tm >= 0.f ? tm : 0.2f * tm;
            rsum[i] = 0.f;
            #pragma unroll
            for (int jj = 0; jj < 2; jj++) {
                float2 sp = unpack2(S2[i][jj]);
                float sval = sp.x + sp.y;
                float w = 0.f;
                int jgl = j0 + cg * 2 + jj;
                if (sval > 0.1f && (r0g + rg * 4 + i) != jgl) {
                    float e0 = aldr + sALS[cg * 2 + jj];
                    float e = e0 >= 0.f ? e0 : 0.2f * e0;
                    w = __expf(e - mrow);
                }
                sW2[(rg * 4 + i) * 33 + cg * 2 + jj] = pack2(w, w);
                rsum[i] += w;
            }
        }
        #pragma unroll
        for (int o = 1; o < 16; o <<= 1)
            #pragma unroll
            for (int i = 0; i < 4; i++)
                rsum[i] += __shfl_xor_sync(0xffffffffu, rsum[i], o);
        if (cg == 0)
            #pragma unroll
            for (int i = 0; i < 4; i++) sDEN[rg * 4 + i] += rsum[i];
        __syncthreads();

        // phase 2: num += W @ HS (packed columns)
        #pragma unroll 2
        for (int j = 0; j < 32; j++) {
            ulonglong2 hA = *(ulonglong2*)&sHSu[j * 64 + cg * 2];
            ulonglong2 hB = *(ulonglong2*)&sHSu[j * 64 + 32 + cg * 2];
            #pragma unroll
            for (int i = 0; i < 4; i++) {
                ull wp = sW2[(rg * 4 + i) * 33 + j];
                fma2(num2[i][0], wp, hA.x); fma2(num2[i][1], wp, hA.y);
                fma2(num2[i][2], wp, hB.x); fma2(num2[i][3], wp, hB.y);
            }
        }
        __syncthreads();
    }
    if (curType >= 0)
        hetero_flush(acc, deng, sDEN, num2, curType, r0g, rg, cg);
}

__global__ void finalize_kernel(float* __restrict__ acc, const float* __restrict__ den,
                                const float* __restrict__ gb) {
    int idx = blockIdx.x * blockDim.x + threadIdx.x;
    if (idx >= 3 * NA * 128) return;
    int c = idx & 127, dr = idx >> 7, type = idx >> 19;
    float d = den[dr], b = gb[type * 128 + c];
    acc[idx] = (d > 0.f) ? acc[idx] / d + b : b;
}

__global__ void attscore_kernel(const float* __restrict__ heter, const float* __restrict__ xt,
                                const float* __restrict__ Watt, const float* __restrict__ atts,
                                float* __restrict__ ssum) {
    int set = blockIdx.y;
    const float* X = (set < 3) ? heter + (size_t)set * NA * 128 : xt;
    int rb = blockIdx.x * 4, t = threadIdx.x, c = t & 63;
    __shared__ float xs[4][128];
    for (int i = t; i < 512; i += 256)
        xs[i >> 7][i & 127] = X[(size_t)(rb + (i >> 7)) * 128 + (i & 127)];
    __syncthreads();
    const float* xr = xs[t >> 6];
    float dot = 0.f;
    #pragma unroll 8
    for (int k = 0; k < 128; k++) dot += xr[k] * Watt[k * 64 + c];
    float val = (1.f / (1.f + __expf(-dot))) * atts[set * 64 + c];
    #pragma unroll
    for (int o = 16; o; o >>= 1) val += __shfl_xor_sync(0xffffffffu, val, o);
    __shared__ float ps[8];
    if ((t & 31) == 0) ps[t >> 5] = val;
    __syncthreads();
    if (t == 0) {
        float s = 0.f;
        #pragma unroll
        for (int i = 0; i < 8; i++) s += ps[i];
        atomicAdd(&ssum[set], s);
    }
}

__global__ void alpha_kernel(const float* __restrict__ ssum, float* __restrict__ alpha) {
    if (threadIdx.x == 0) {
        float s[4], m = -3e38f;
        for (int i = 0; i < 4; i++) { s[i] = ssum[i] / (float)NA; m = fmaxf(m, s[i]); }
        float e[4], tot = 0.f;
        for (int i = 0; i < 4; i++) { e[i] = expf(s[i] - m); tot += e[i]; }
        for (int i = 0; i < 4; i++) alpha[i] = e[i] / tot;
    }
}

__global__ void xatt_kernel(const float* __restrict__ heter, const float* __restrict__ xt,
                            const float* __restrict__ alpha, float* __restrict__ out) {
    int idx = blockIdx.x * blockDim.x + threadIdx.x;
    if (idx >= NA * 128) return;
    out[idx] = alpha[0] * heter[idx] + alpha[1] * heter[NA * 128 + idx] +
               alpha[2] * heter[2 * NA * 128 + idx] + alpha[3] * xt[idx];
}

__global__ void deg_kernel(const int* __restrict__ dst, float* __restrict__ deg, int E) {
    int e = blockIdx.x * blockDim.x + threadIdx.x;
    if (e < E) atomicAdd(&deg[dst[e]], 1.0f);
}

__global__ void scatter_kernel(const float* __restrict__ X, const int* __restrict__ src,
                               const int* __restrict__ dst, float* __restrict__ AGG,
                               int E, int C) {
    int idx = blockIdx.x * blockDim.x + threadIdx.x;
    int per = C >> 2;
    if (idx >= E * per) return;
    int e = idx / per, q = idx - e * per;
    int s = src[e], d = dst[e];
    float4 v = *(const float4*)&X[(size_t)s * C + q * 4];
    float* o = &AGG[(size_t)d * C + q * 4];
    atomicAdd(o + 0, v.x); atomicAdd(o + 1, v.y);
    atomicAdd(o + 2, v.z); atomicAdd(o + 3, v.w);
}

__global__ void rowdiv_kernel(float* __restrict__ AGG, const float* __restrict__ deg,
                              int n, int C) {
    int idx = blockIdx.x * blockDim.x + threadIdx.x;
    if (idx >= n) return;
    AGG[idx] = AGG[idx] / fmaxf(deg[idx / C], 1.0f);
}

extern "C" void kernel_launch(void* const* d_in, const int* in_sizes, int n_in,
                              void* d_out, int out_size) {
    const float* x_ma = (const float*)d_in[0];
    const float* x_mp = (const float*)d_in[1];
    const float* x_mt = (const float*)d_in[2];
    const float* x_mc = (const float*)d_in[3];
    const float* x_ia = (const float*)d_in[4];
    const int*   edge = (const int*)d_in[5];
    const float* Wla  = (const float*)d_in[6];  const float* bla  = (const float*)d_in[7];
    const float* Wlp  = (const float*)d_in[8];  const float* blp  = (const float*)d_in[9];
    const float* Wlt  = (const float*)d_in[10]; const float* blt  = (const float*)d_in[11];
    const float* Wlc  = (const float*)d_in[12]; const float* blc  = (const float*)d_in[13];
    const float* Wltg = (const float*)d_in[14]; const float* bltg = (const float*)d_in[15];
    const float* gWs  = (const float*)d_in[16];
    const float* gWd  = (const float*)d_in[17];
    const float* gas  = (const float*)d_in[18];
    const float* gad  = (const float*)d_in[19];
    const float* gb   = (const float*)d_in[20];
    const float* Watt = (const float*)d_in[21];
    const float* atts = (const float*)d_in[22];
    const float* W1l  = (const float*)d_in[23]; const float* b1 = (const float*)d_in[24];
    const float* W1r  = (const float*)d_in[25];
    const float* W2l  = (const float*)d_in[26]; const float* b2 = (const float*)d_in[27];
    const float* W2r  = (const float*)d_in[28];

    int E = in_sizes[5] / 2;
    int Ka = in_sizes[0] / NA, Kp = in_sizes[1] / NP, Kt = in_sizes[2] / NT;
    int Kc = in_sizes[3] / NC, Kg = in_sizes[4] / NA;

    float* out_x   = (float*)d_out;
    float* out_att = (float*)d_out + (size_t)NA * 64;

    float *ha,*hp,*ht,*hc,*xt,*an,*snp,*snt,*snc,*gp,*gt,*gc;
    float *alsp,*alst,*alsc,*ald,*wdv,*acc,*den,*ssum,*alpha,*agg1,*deg,*h1,*q,*aggq;
    unsigned* mxsEnc;
    cudaGetSymbolAddress((void**)&ha,g_ha);   cudaGetSymbolAddress((void**)&hp,g_hp);
    cudaGetSymbolAddress((void**)&ht,g_ht);   cudaGetSymbolAddress((void**)&hc,g_hc);
    cudaGetSymbolAddress((void**)&xt,g_xt);   cudaGetSymbolAddress((void**)&an,g_an);
    cudaGetSymbolAddress((void**)&snp,g_snp); cudaGetSymbolAddress((void**)&snt,g_snt);
    cudaGetSymbolAddress((void**)&snc,g_snc); cudaGetSymbolAddress((void**)&gp,g_gp);
    cudaGetSymbolAddress((void**)&gt,g_gt);   cudaGetSymbolAddress((void**)&gc,g_gc);
    cudaGetSymbolAddress((void**)&alsp,g_alsp); cudaGetSymbolAddress((void**)&alst,g_alst);
    cudaGetSymbolAddress((void**)&alsc,g_alsc); cudaGetSymbolAddress((void**)&ald,g_ald);
    cudaGetSymbolAddress((void**)&wdv,g_wdv);   cudaGetSymbolAddress((void**)&mxsEnc,g_mxsEnc);
    cudaGetSymbolAddress((void**)&acc,g_acc);   cudaGetSymbolAddress((void**)&den,g_den);
    cudaGetSymbolAddress((void**)&ssum,g_ssum); cudaGetSymbolAddress((void**)&alpha,g_alpha);
    cudaGetSymbolAddress((void**)&agg1,g_agg1); cudaGetSymbolAddress((void**)&deg,g_deg);
    cudaGetSymbolAddress((void**)&h1,g_h1);     cudaGetSymbolAddress((void**)&q,g_q);
    cudaGetSymbolAddress((void**)&aggq,g_aggq);

    auto mkjob = [](const float*A,const float*W,const float*A2,const float*W2,
                    const float*bias,const float*addD,const float*degp,float*C,
                    int M,int K,int K2,int N,int relu,int colBlks,int blkStart){
        LJob J; J.A=A;J.W=W;J.A2=A2;J.W2=W2;J.bias=bias;J.addD=addD;J.degp=degp;J.C=C;
        J.M=M;J.K=K;J.K2=K2;J.N=N;J.relu=relu;J.colBlks=colBlks;J.blkStart=blkStart;
        return J;
    };

    // 1: wvec (independent of everything else)
    wvec_kernel<<<3,128>>>(gWd, gad, wdv);
    // 2: fused zero init
    zero_all<<<9281,256>>>(acc, agg1, aggq, den, deg, ssum, mxsEnc);
    // 3: batched dimension transforms (5 GEMMs, 352 blocks)
    {
        LJobs B; B.n = 5;
        B.j[0] = mkjob(x_ma, Wla,  0,0, bla,  0,0, ha, NA, Ka, 0, 128, 0, 1, 0);
        B.j[1] = mkjob(x_mp, Wlp,  0,0, blp,  0,0, hp, NP, Kp, 0, 128, 0, 1, 64);
        B.j[2] = mkjob(x_mt, Wlt,  0,0, blt,  0,0, ht, NT, Kt, 0, 128, 0, 1, 192);
        B.j[3] = mkjob(x_mc, Wlc,  0,0, blc,  0,0, hc, NC, Kc, 0, 128, 0, 1, 256);
        B.j[4] = mkjob(x_ia, Wltg, 0,0, bltg, 0,0, xt, NA, Kg, 0, 128, 0, 1, 288);
        lin_batch<<<352,256>>>(B);
    }
    // 4: batched GAT source transforms (3 GEMMs, 224 blocks)
    {
        LJobs B; B.n = 3;
        B.j[0] = mkjob(hp, gWs + 0*16384, 0,0, 0,0,0, gp, NP, 128, 0, 128, 0, 1, 0);
        B.j[1] = mkjob(ht, gWs + 1*16384, 0,0, 0,0,0, gt, NT, 128, 0, 128, 0, 1, 128);
        B.j[2] = mkjob(hc, gWs + 2*16384, 0,0, 0,0,0, gc, NC, 128, 0, 128, 0, 1, 192);
        lin_batch<<<224,256>>>(B);
    }
    // 5: fused rownorms + matvecs + max
    prep_all<<<45056,128>>>(ha, hp, ht, hc, an, snp, snt, snc,
                            gp, gt, gc, wdv, gas, ald, alsp, alst, alsc, mxsEnc);
    // 6: persistent fused hetero GAT  (profiled by ncu -s 5 -c 1)
    cudaFuncSetAttribute(hetero_kernel, cudaFuncAttributeMaxDynamicSharedMemorySize, 84096);
    hetero_kernel<<<HET_GRID,256,84096>>>(an, ald, mxsEnc, snp, gp, alsp,
                                          snt, gt, alst, snc, gc, alsc, acc, den);
    // epilogue
    finalize_kernel<<<(3*NA*128)/256,256>>>(acc, den, gb);
    attscore_kernel<<<dim3(NA/4,4),256>>>(acc, xt, Watt, atts, ssum);
    alpha_kernel<<<1,32>>>(ssum, alpha);
    xatt_kernel<<<(NA*128)/256,256>>>(acc, xt, alpha, out_att);
    // GraphSAGE
    deg_kernel<<<(E+255)/256,256>>>(edge + E, deg, E);
    scatter_kernel<<<(E*32)/256,256>>>(ha, edge, edge + E, agg1, E, 128);
    rowdiv_kernel<<<(NA*128)/256,256>>>(agg1, deg, NA*128, 128);
    {   // h1 = relu(agg1@W1l + b1 + ha@W1r)  (dual GEMM, 128 blocks)
        LJobs B; B.n = 1;
        B.j[0] = mkjob(agg1, W1l, ha, W1r, b1, 0,0, h1, NA, 128, 128, 256, 1, 2, 0);
        lin_batch<<<128,256>>>(B);
    }
    {   // q = h1@W2l  (64 blocks)
        LJobs B; B.n = 1;
        B.j[0] = mkjob(h1, W2l, 0,0, 0,0,0, q, NA, 256, 0, 64, 0, 1, 0);
        lin_batch<<<64,256>>>(B);
    }
    scatter_kernel<<<(E*16)/256,256>>>(q, edge, edge + E, aggq, E, 64);
    {   // out_x = h1@W2r + b2 + aggq/deg  (64 blocks)
        LJobs B; B.n = 1;
        B.j[0] = mkjob(h1, W2r, 0,0, b2, aggq, deg, out_x, NA, 256, 0, 64, 0, 1, 0);
        lin_batch<<<64,256>>>(B);
    }
}